// round 2
// baseline (speedup 1.0000x reference)
#include <cuda_runtime.h>
#include <cuda_fp16.h>

#define SEQ    8192
#define DIN    256
#define H      2048
#define FOURH  8192
#define DOUT   64
#define GRID_LSTM 148
#define NTHREADS  256

// ---- static scratch (no allocations allowed) ----
__device__ __align__(16) float g_xg[(size_t)SEQ * FOURH];   // 256 MB
__device__ __align__(16) float g_hs[(size_t)SEQ * H];       // 64 MB
__device__ __align__(16) float g_hbuf[H];
__device__ unsigned g_count;
__device__ unsigned g_phase;

// SMEM layout for LSTM kernel (bytes):
//   [0,229376)          half2 weights: 14 units * 4 gates * 1024 half2
//   [229376,231424)     h chunk: 512 floats
//   [231424,231680)     zbuf: 64 floats
//   [231680,231744)     cbuf: 16 floats
#define LSTM_SMEM 231744

// ============================================================
// Kernel 1: xg[t, r] = x[t,:] . W_ih[r,:] + (b_ih[r]+b_hh[r])
// 64x64 block tile, 4x4 per thread, K-chunks of 64.
// ============================================================
__global__ void xg_gemm(const float* __restrict__ x, const float* __restrict__ Wih,
                        const float* __restrict__ bih, const float* __restrict__ bhh) {
    __shared__ float sA[64][65];   // [k][m]  (t rows)
    __shared__ float sB[64][65];   // [k][n]  (4H rows)
    const int bm = blockIdx.y * 64;     // t
    const int bn = blockIdx.x * 64;     // gate-row
    const int tid = threadIdx.x;
    const int tm = tid & 15, tn = tid >> 4;

    float acc[4][4];
#pragma unroll
    for (int i = 0; i < 4; i++)
#pragma unroll
        for (int j = 0; j < 4; j++) acc[i][j] = 0.f;

    for (int kc = 0; kc < DIN; kc += 64) {
#pragma unroll
        for (int i = 0; i < 16; i++) {
            int e = tid + i * 256;
            int row = e >> 6, col = e & 63;
            sA[col][row] = x[(size_t)(bm + row) * DIN + kc + col];
            sB[col][row] = Wih[(size_t)(bn + row) * DIN + kc + col];
        }
        __syncthreads();
#pragma unroll 16
        for (int kk = 0; kk < 64; kk++) {
            float a[4], b[4];
#pragma unroll
            for (int i = 0; i < 4; i++) a[i] = sA[kk][tm * 4 + i];
#pragma unroll
            for (int j = 0; j < 4; j++) b[j] = sB[kk][tn * 4 + j];
#pragma unroll
            for (int i = 0; i < 4; i++)
#pragma unroll
                for (int j = 0; j < 4; j++) acc[i][j] += a[i] * b[j];
        }
        __syncthreads();
    }
#pragma unroll
    for (int j = 0; j < 4; j++) {
        int n = bn + tn * 4 + j;
        float bias = bih[n] + bhh[n];
#pragma unroll
        for (int i = 0; i < 4; i++) {
            int m = bm + tm * 4 + i;
            g_xg[(size_t)m * FOURH + n] = acc[i][j] + bias;
        }
    }
}

// ============================================================
// Kernel 2: persistent LSTM recurrence.
// 148 CTAs (1/SM), each owns 14 (first 124) or 13 (last 24) hidden units.
// W_hh rows for owned units cached in SMEM as fp16; fp32 accumulate.
// One software grid barrier per timestep.
// ============================================================
__global__ void __launch_bounds__(NTHREADS, 1)
lstm_kernel(const float* __restrict__ Whh, const float* __restrict__ hprev,
            const float* __restrict__ cprev,
            float* __restrict__ out_hT, float* __restrict__ out_cT) {
    extern __shared__ char smem[];
    __half2* wsm  = (__half2*)smem;                       // [nrows][1024]
    float*   hch  = (float*)(smem + 229376);              // 512 floats
    float*   zbuf = (float*)(smem + 231424);              // 64 floats
    float*   cbuf = (float*)(smem + 231680);              // 16 floats

    const int cta = blockIdx.x;
    const int tid = threadIdx.x;
    const int warp = tid >> 5, lane = tid & 31;
    const int ucount = (cta < 124) ? 14 : 13;
    const int ustart = (cta < 124) ? 14 * cta : (1736 + 13 * (cta - 124));
    const int nrows = 4 * ucount;

    // ---- one-time: load owned W_hh rows as half2 into SMEM ----
    for (int p = tid; p < nrows * 1024; p += NTHREADS) {
        int lr = p >> 10, c = p & 1023;
        int u = lr >> 2, g = lr & 3;
        int grow = g * H + ustart + u;
        const float* wp = Whh + (size_t)grow * H + 2 * c;
        wsm[p] = __floats2half2_rn(wp[0], wp[1]);
    }
    unsigned base = 0;
    if (tid == 0) base = *((volatile unsigned*)&g_phase);
    __syncthreads();

    float acc[7];
    for (int t = 0; t < SEQ; t++) {
        // prefetch xg for owned units (independent of h -> hides DRAM latency)
        float xg0 = 0.f, xg1 = 0.f, xg2 = 0.f, xg3 = 0.f;
        if (tid < ucount) {
            int j = ustart + tid;
            const float* xr = g_xg + (size_t)t * FOURH;
            xg0 = __ldg(xr + j);
            xg1 = __ldg(xr + H + j);
            xg2 = __ldg(xr + 2 * H + j);
            xg3 = __ldg(xr + 3 * H + j);
        }
#pragma unroll
        for (int i = 0; i < 7; i++) acc[i] = 0.f;

        const float* hsrc = (t == 0) ? hprev : g_hbuf;
#pragma unroll 1
        for (int c4 = 0; c4 < 4; c4++) {
            // stage 512-float h chunk into SMEM (L2-coherent read, bypass L1)
            const float2* src = (const float2*)(hsrc + c4 * 512) + tid;
            float2 hv = __ldcg(src);
            ((float2*)hch)[tid] = hv;
            __syncthreads();
#pragma unroll
            for (int k = 0; k < 8; k++) {
                float2 h2 = ((const float2*)hch)[k * 32 + lane];
#pragma unroll
                for (int i = 0; i < 7; i++) {
                    int lr = warp + i * 8;
                    if (lr < nrows) {
                        float2 w = __half22float2(wsm[lr * 1024 + c4 * 256 + k * 32 + lane]);
                        acc[i] = fmaf(w.x, h2.x, acc[i]);
                        acc[i] = fmaf(w.y, h2.y, acc[i]);
                    }
                }
            }
            __syncthreads();
        }

        // warp-reduce each row, deposit into zbuf
#pragma unroll
        for (int i = 0; i < 7; i++) {
            int lr = warp + i * 8;
            float v = acc[i];
#pragma unroll
            for (int o = 16; o > 0; o >>= 1) v += __shfl_xor_sync(0xffffffffu, v, o);
            if (lane == 0 && lr < nrows) zbuf[lr] = v;
        }
        __syncthreads();

        // gate math + state update for owned units
        if (tid < ucount) {
            int j = ustart + tid;
            float zi = xg0 + zbuf[tid * 4 + 0];
            float zf = xg1 + zbuf[tid * 4 + 1];
            float zg = xg2 + zbuf[tid * 4 + 2];
            float zo = xg3 + zbuf[tid * 4 + 3];
            float ig = 1.f / (1.f + __expf(-zi));
            float fg = 1.f / (1.f + __expf(-zf));
            float gg = tanhf(zg);
            float og = 1.f / (1.f + __expf(-zo));
            float cold = (t == 0) ? cprev[j] : cbuf[tid];
            float cv = fg * cold + ig * gg;
            float hv = og * tanhf(cv);
            cbuf[tid] = cv;
            __stcg(&g_hbuf[j], hv);
            g_hs[(size_t)t * H + j] = hv;
            if (t == SEQ - 1) { out_hT[j] = hv; out_cT[j] = cv; }
        }
        __syncthreads();

        // grid barrier (sense via monotone phase counter; wrap-safe)
        if (tid == 0) {
            __threadfence();
            unsigned want = base + (unsigned)t + 1u;
            unsigned old = atomicAdd(&g_count, 1u);
            if (old == GRID_LSTM - 1) {
                atomicExch(&g_count, 0u);
                __threadfence();
                atomicAdd(&g_phase, 1u);
            } else {
                const volatile unsigned* vp = &g_phase;
                while ((int)(*vp - want) < 0) { }
            }
        }
        __syncthreads();
    }
}

// ============================================================
// Kernel 3: out[t,d] = sigmoid(hs[t,:] . W_fc[d,:] + b_fc[d])
// ============================================================
__global__ void fc_kernel(const float* __restrict__ Wfc, const float* __restrict__ bfc,
                          float* __restrict__ out) {
    __shared__ float sH[64][65];
    __shared__ float sW[64][65];
    const int t0 = blockIdx.x * 64;
    const int tid = threadIdx.x;
    const int r = tid >> 2;    // 0..63 (t within tile)
    const int cg = tid & 3;    // 0..3  (16 outputs each)

    float acc[16];
#pragma unroll
    for (int c = 0; c < 16; c++) acc[c] = 0.f;

    for (int kc = 0; kc < H; kc += 64) {
#pragma unroll
        for (int i = 0; i < 16; i++) {
            int e = tid + i * 256;
            int row = e >> 6, col = e & 63;
            sH[row][col] = g_hs[(size_t)(t0 + row) * H + kc + col];
            sW[row][col] = Wfc[(size_t)row * H + kc + col];
        }
        __syncthreads();
#pragma unroll 16
        for (int kk = 0; kk < 64; kk++) {
            float hv = sH[r][kk];
#pragma unroll
            for (int c = 0; c < 16; c++)
                acc[c] = fmaf(hv, sW[cg * 16 + c][kk], acc[c]);
        }
        __syncthreads();
    }
#pragma unroll
    for (int c = 0; c < 16; c++) {
        int d = cg * 16 + c;
        float v = acc[c] + bfc[d];
        out[(size_t)(t0 + r) * DOUT + d] = 1.f / (1.f + __expf(-v));
    }
}

// ============================================================
extern "C" void kernel_launch(void* const* d_in, const int* in_sizes, int n_in,
                              void* d_out, int out_size) {
    const float* x     = (const float*)d_in[0];
    const float* hprev = (const float*)d_in[1];
    const float* cprev = (const float*)d_in[2];
    const float* Wih   = (const float*)d_in[3];
    const float* Whh   = (const float*)d_in[4];
    const float* bih   = (const float*)d_in[5];
    const float* bhh   = (const float*)d_in[6];
    const float* Wfc   = (const float*)d_in[7];
    const float* bfc   = (const float*)d_in[8];

    float* out    = (float*)d_out;                       // [SEQ, DOUT]
    float* out_hT = out + (size_t)SEQ * DOUT;            // [H]
    float* out_cT = out_hT + H;                          // [H]

    cudaFuncSetAttribute(lstm_kernel, cudaFuncAttributeMaxDynamicSharedMemorySize,
                         LSTM_SMEM);

    dim3 g1(FOURH / 64, SEQ / 64);
    xg_gemm<<<g1, 256>>>(x, Wih, bih, bhh);
    lstm_kernel<<<GRID_LSTM, NTHREADS, LSTM_SMEM>>>(Whh, hprev, cprev, out_hT, out_cT);
    fc_kernel<<<SEQ / 64, 256>>>(Wfc, bfc, out);
}

// round 3
// speedup vs baseline: 1.3520x; 1.3520x over previous
#include <cuda_runtime.h>
#include <cuda_fp16.h>

#define SEQ    8192
#define DIN    256
#define H      2048
#define FOURH  8192
#define DOUT   64
#define GRID_LSTM 148
#define NTHREADS  256

#define KREG   14            // half2 chunks per row held in registers
#define KSMEM  (32 - KREG)   // half2 chunks per row held in SMEM

// ---- static scratch (no allocations allowed) ----
__device__ __align__(16) float g_xg[(size_t)SEQ * FOURH];   // 256 MB
__device__ __align__(16) float g_hs[(size_t)SEQ * H];       // 64 MB
__device__ __align__(16) unsigned short g_hbuf[2][H];       // h as fp16, double-buffered
__device__ unsigned g_count;
__device__ unsigned g_phase;

// SMEM layout (bytes):
//   [0, 56*KSMEM*32*4)   weight half2, SMEM-resident chunks
//   then 4096            h as half (2048 x fp16)
//   then 256             zbuf (56 rows used)
//   then 64              cbuf (14 units)
#define WSM_BYTES (56 * KSMEM * 32 * 4)
#define HSM_OFF   WSM_BYTES
#define ZBUF_OFF  (HSM_OFF + 4096)
#define CBUF_OFF  (ZBUF_OFF + 256)
#define LSTM_SMEM (CBUF_OFF + 64)

// ============================================================
// Kernel 1: xg[t, r] = x[t,:] . W_ih[r,:] + (b_ih[r]+b_hh[r])
// ============================================================
__global__ void xg_gemm(const float* __restrict__ x, const float* __restrict__ Wih,
                        const float* __restrict__ bih, const float* __restrict__ bhh) {
    __shared__ float sA[64][65];   // [k][m]
    __shared__ float sB[64][65];   // [k][n]
    const int bm = blockIdx.y * 64;
    const int bn = blockIdx.x * 64;
    const int tid = threadIdx.x;
    const int tm = tid & 15, tn = tid >> 4;

    float acc[4][4];
#pragma unroll
    for (int i = 0; i < 4; i++)
#pragma unroll
        for (int j = 0; j < 4; j++) acc[i][j] = 0.f;

    for (int kc = 0; kc < DIN; kc += 64) {
#pragma unroll
        for (int i = 0; i < 16; i++) {
            int e = tid + i * 256;
            int row = e >> 6, col = e & 63;
            sA[col][row] = x[(size_t)(bm + row) * DIN + kc + col];
            sB[col][row] = Wih[(size_t)(bn + row) * DIN + kc + col];
        }
        __syncthreads();
#pragma unroll 16
        for (int kk = 0; kk < 64; kk++) {
            float a[4], b[4];
#pragma unroll
            for (int i = 0; i < 4; i++) a[i] = sA[kk][tm * 4 + i];
#pragma unroll
            for (int j = 0; j < 4; j++) b[j] = sB[kk][tn * 4 + j];
#pragma unroll
            for (int i = 0; i < 4; i++)
#pragma unroll
                for (int j = 0; j < 4; j++) acc[i][j] += a[i] * b[j];
        }
        __syncthreads();
    }
#pragma unroll
    for (int j = 0; j < 4; j++) {
        int n = bn + tn * 4 + j;
        float bias = bih[n] + bhh[n];
#pragma unroll
        for (int i = 0; i < 4; i++) {
            int m = bm + tm * 4 + i;
            g_xg[(size_t)m * FOURH + n] = acc[i][j] + bias;
        }
    }
}

// ============================================================
// Kernel 2: persistent LSTM recurrence (HFMA2, hybrid reg/SMEM weights)
// 148 CTAs, CTA owns 14 (or 13) units = 56 (52) W_hh rows.
// Warp w owns local rows [7w, 7w+7). Lane l owns half2 cols {l+32k}.
// k in [0,KREG): weights in registers; k in [KREG,32): weights in SMEM.
// ============================================================
__global__ void __launch_bounds__(NTHREADS, 1)
lstm_kernel(const float* __restrict__ Whh, const float* __restrict__ hprev,
            const float* __restrict__ cprev,
            float* __restrict__ out_hT, float* __restrict__ out_cT) {
    extern __shared__ char smem[];
    __half2* wsm  = (__half2*)smem;                    // [56][KSMEM][32]
    __half*  hsm  = (__half*)(smem + HSM_OFF);         // 2048 halves
    __half2* hsm2 = (__half2*)hsm;
    float*   zbuf = (float*)(smem + ZBUF_OFF);
    float*   cbuf = (float*)(smem + CBUF_OFF);

    const int cta = blockIdx.x;
    const int tid = threadIdx.x;
    const int warp = tid >> 5, lane = tid & 31;
    const int ucount = (cta < 124) ? 14 : 13;
    const int ustart = (cta < 124) ? 14 * cta : (1736 + 13 * (cta - 124));
    const int nrows = 4 * ucount;

    // ---- one-time: load owned W_hh rows (fp16). reg part + SMEM part ----
    __half2 wreg[7][KREG];
#pragma unroll
    for (int r = 0; r < 7; r++) {
        int lr = warp * 7 + r;
        bool valid = lr < nrows;
        int u = lr >> 2, g = lr & 3;
        const float* wp = Whh + (size_t)(g * H + ustart + u) * H;
#pragma unroll
        for (int k = 0; k < KREG; k++) {
            int c = lane + 32 * k;
            wreg[r][k] = valid ? __floats2half2_rn(wp[2 * c], wp[2 * c + 1])
                               : __floats2half2_rn(0.f, 0.f);
        }
#pragma unroll
        for (int k2 = 0; k2 < KSMEM; k2++) {
            int c = lane + 32 * (KREG + k2);
            wsm[(lr * KSMEM + k2) * 32 + lane] =
                valid ? __floats2half2_rn(wp[2 * c], wp[2 * c + 1])
                      : __floats2half2_rn(0.f, 0.f);
        }
    }
    unsigned base = 0;
    if (tid == 0) base = *((volatile unsigned*)&g_phase);
    __syncthreads();

    for (int t = 0; t < SEQ; t++) {
        // xg prefetch for owned units (independent of h)
        float xg0 = 0.f, xg1 = 0.f, xg2 = 0.f, xg3 = 0.f;
        if (tid < ucount) {
            int j = ustart + tid;
            const float* xr = g_xg + (size_t)t * FOURH;
            xg0 = __ldg(xr + j);
            xg1 = __ldg(xr + H + j);
            xg2 = __ldg(xr + 2 * H + j);
            xg3 = __ldg(xr + 3 * H + j);
        }

        // stage h (fp16) into SMEM in one shot
        if (t == 0) {
#pragma unroll
            for (int i = 0; i < 8; i++)
                hsm[tid * 8 + i] = __float2half_rn(hprev[tid * 8 + i]);
        } else {
            ((uint4*)hsm)[tid] = __ldcg((const uint4*)g_hbuf[t & 1] + tid);
        }
        __syncthreads();

        // matvec: 7 rows/warp, fp16 accumulate in groups of 8 half2, flush to fp32
        float2 facc[7];
#pragma unroll
        for (int r = 0; r < 7; r++) { facc[r].x = 0.f; facc[r].y = 0.f; }

#pragma unroll
        for (int grp = 0; grp < 4; grp++) {
            __half2 hacc[7];
#pragma unroll
            for (int r = 0; r < 7; r++) hacc[r] = __floats2half2_rn(0.f, 0.f);
#pragma unroll
            for (int kk = 0; kk < 8; kk++) {
                const int k = grp * 8 + kk;
                __half2 h2 = hsm2[32 * k + lane];
#pragma unroll
                for (int r = 0; r < 7; r++) {
                    __half2 w;
                    if (k < KREG) {
                        w = wreg[r][k];
                    } else {
                        w = wsm[((warp * 7 + r) * KSMEM + (k - KREG)) * 32 + lane];
                    }
                    hacc[r] = __hfma2(w, h2, hacc[r]);
                }
            }
#pragma unroll
            for (int r = 0; r < 7; r++) {
                facc[r].x += __low2float(hacc[r]);
                facc[r].y += __high2float(hacc[r]);
            }
        }

        // warp reduce each row into zbuf
#pragma unroll
        for (int r = 0; r < 7; r++) {
            float v = facc[r].x + facc[r].y;
#pragma unroll
            for (int o = 16; o > 0; o >>= 1) v += __shfl_xor_sync(0xffffffffu, v, o);
            int lr = warp * 7 + r;
            if (lane == 0 && lr < nrows) zbuf[lr] = v;
        }
        __syncthreads();

        // gates + state update for owned units
        if (tid < ucount) {
            int j = ustart + tid;
            float zi = xg0 + zbuf[tid * 4 + 0];
            float zf = xg1 + zbuf[tid * 4 + 1];
            float zg = xg2 + zbuf[tid * 4 + 2];
            float zo = xg3 + zbuf[tid * 4 + 3];
            float ig = 1.f / (1.f + __expf(-zi));
            float fg = 1.f / (1.f + __expf(-zf));
            float gg = tanhf(zg);
            float og = 1.f / (1.f + __expf(-zo));
            float cold = (t == 0) ? cprev[j] : cbuf[tid];
            float cv = fg * cold + ig * gg;
            float hv = og * tanhf(cv);
            cbuf[tid] = cv;
            g_hbuf[(t + 1) & 1][j] = __half_as_ushort(__float2half_rn(hv));
            g_hs[(size_t)t * H + j] = hv;
            if (t == SEQ - 1) { out_hT[j] = hv; out_cT[j] = cv; }
        }
        __syncthreads();

        // grid barrier (monotone phase counter; wrap-safe)
        if (tid == 0) {
            __threadfence();
            unsigned want = base + (unsigned)t + 1u;
            unsigned old = atomicAdd(&g_count, 1u);
            if (old == GRID_LSTM - 1) {
                atomicExch(&g_count, 0u);
                __threadfence();
                atomicAdd(&g_phase, 1u);
            } else {
                const volatile unsigned* vp = &g_phase;
                while ((int)(*vp - want) < 0) { }
            }
            __threadfence();
        }
        __syncthreads();
    }
}

// ============================================================
// Kernel 3: out[t,d] = sigmoid(hs[t,:] . W_fc[d,:] + b_fc[d])
// ============================================================
__global__ void fc_kernel(const float* __restrict__ Wfc, const float* __restrict__ bfc,
                          float* __restrict__ out) {
    __shared__ float sH[64][65];
    __shared__ float sW[64][65];
    const int t0 = blockIdx.x * 64;
    const int tid = threadIdx.x;
    const int r = tid >> 2;
    const int cg = tid & 3;

    float acc[16];
#pragma unroll
    for (int c = 0; c < 16; c++) acc[c] = 0.f;

    for (int kc = 0; kc < H; kc += 64) {
#pragma unroll
        for (int i = 0; i < 16; i++) {
            int e = tid + i * 256;
            int row = e >> 6, col = e & 63;
            sH[row][col] = g_hs[(size_t)(t0 + row) * H + kc + col];
            sW[row][col] = Wfc[(size_t)row * H + kc + col];
        }
        __syncthreads();
#pragma unroll 16
        for (int kk = 0; kk < 64; kk++) {
            float hv = sH[r][kk];
#pragma unroll
            for (int c = 0; c < 16; c++)
                acc[c] = fmaf(hv, sW[cg * 16 + c][kk], acc[c]);
        }
        __syncthreads();
    }
#pragma unroll
    for (int c = 0; c < 16; c++) {
        int d = cg * 16 + c;
        float v = acc[c] + bfc[d];
        out[(size_t)(t0 + r) * DOUT + d] = 1.f / (1.f + __expf(-v));
    }
}

// ============================================================
extern "C" void kernel_launch(void* const* d_in, const int* in_sizes, int n_in,
                              void* d_out, int out_size) {
    const float* x     = (const float*)d_in[0];
    const float* hprev = (const float*)d_in[1];
    const float* cprev = (const float*)d_in[2];
    const float* Wih   = (const float*)d_in[3];
    const float* Whh   = (const float*)d_in[4];
    const float* bih   = (const float*)d_in[5];
    const float* bhh   = (const float*)d_in[6];
    const float* Wfc   = (const float*)d_in[7];
    const float* bfc   = (const float*)d_in[8];

    float* out    = (float*)d_out;
    float* out_hT = out + (size_t)SEQ * DOUT;
    float* out_cT = out_hT + H;

    cudaFuncSetAttribute(lstm_kernel, cudaFuncAttributeMaxDynamicSharedMemorySize,
                         LSTM_SMEM);

    dim3 g1(FOURH / 64, SEQ / 64);
    xg_gemm<<<g1, 256>>>(x, Wih, bih, bhh);
    lstm_kernel<<<GRID_LSTM, NTHREADS, LSTM_SMEM>>>(Whh, hprev, cprev, out_hT, out_cT);
    fc_kernel<<<SEQ / 64, 256>>>(Wfc, bfc, out);
}